// round 3
// baseline (speedup 1.0000x reference)
#include <cuda_runtime.h>
#include <math.h>

namespace {
constexpr int Bsz = 256;   // batch
constexpr int Tt  = 200;   // time steps
constexpr int Xd  = 128;   // input dim
constexpr int Hd  = 512;   // hidden
constexpr int NU  = 100;   // bottleneck
constexpr int CIN = 2 * Hd + Xd;   // 1152
constexpr int RPB = 2;             // batch rows per CTA
constexpr int NBLK = Bsz / RPB;    // 128 CTAs
constexpr int NTHR = 256;
}

struct SMem {
    float h[RPB][Hd];
    float hs[RPB][Hd];
    float hode[RPB][Hd];
    float ug[RPB][Hd];
    float rg[RPB][Hd];
    float cc[RPB][CIN];
    float xv[RPB][Xd];
    float t1[RPB][NU];
    float p1[RPB][NU];
    float p2[RPB][NU];
    float dt;
};

__device__ __forceinline__ float sigmoidf_(float x) {
    return 1.0f / (1.0f + expf(-x));
}

// dot over K of smem vector `in` with column j of row-major W (K x ldw)
template <int K>
__device__ __forceinline__ float dotN(const float* __restrict__ in,
                                      const float* __restrict__ W,
                                      int ldw, int j) {
    float a0 = 0.f, a1 = 0.f, a2 = 0.f, a3 = 0.f;
#pragma unroll 4
    for (int k = 0; k < K; k += 4) {
        a0 = fmaf(in[k + 0], __ldg(&W[(k + 0) * ldw + j]), a0);
        a1 = fmaf(in[k + 1], __ldg(&W[(k + 1) * ldw + j]), a1);
        a2 = fmaf(in[k + 2], __ldg(&W[(k + 2) * ldw + j]), a2);
        a3 = fmaf(in[k + 3], __ldg(&W[(k + 3) * ldw + j]), a3);
    }
    return (a0 + a1) + (a2 + a3);
}

// rows i0v,i1v (len 100) x W(100 x 512) -> 4 accumulators for cols t, t+256
__device__ __forceinline__ void mm100_512(const float* __restrict__ i0v,
                                          const float* __restrict__ i1v,
                                          const float* __restrict__ W, int t,
                                          float& a00, float& a01, float& a10, float& a11) {
    const int j0 = t, j1 = t + 256;
    a00 = a01 = a10 = a11 = 0.f;
#pragma unroll 5
    for (int k = 0; k < NU; k++) {
        float w0 = __ldg(&W[k * Hd + j0]);
        float w1 = __ldg(&W[k * Hd + j1]);
        float x0 = i0v[k], x1 = i1v[k];
        a00 = fmaf(x0, w0, a00); a01 = fmaf(x0, w1, a01);
        a10 = fmaf(x1, w0, a10); a11 = fmaf(x1, w1, a11);
    }
}

// rows i0v,i1v (len 100) x W(100 x 1024) -> 8 accumulators, cols t+256*q
__device__ __forceinline__ void mm100_1024(const float* __restrict__ i0v,
                                           const float* __restrict__ i1v,
                                           const float* __restrict__ W, int t,
                                           float a[8]) {
#pragma unroll
    for (int q = 0; q < 8; q++) a[q] = 0.f;
#pragma unroll 5
    for (int k = 0; k < NU; k++) {
        const float* Wk = W + k * 1024 + t;
        float w0 = __ldg(Wk + 0);
        float w1 = __ldg(Wk + 256);
        float w2 = __ldg(Wk + 512);
        float w3 = __ldg(Wk + 768);
        float x0 = i0v[k], x1 = i1v[k];
        a[0] = fmaf(x0, w0, a[0]); a[1] = fmaf(x0, w1, a[1]);
        a[2] = fmaf(x0, w2, a[2]); a[3] = fmaf(x0, w3, a[3]);
        a[4] = fmaf(x1, w0, a[4]); a[5] = fmaf(x1, w1, a[5]);
        a[6] = fmaf(x1, w2, a[6]); a[7] = fmaf(x1, w3, a[7]);
    }
}

__global__ void __launch_bounds__(NTHR, 1)
ode_gru_kernel(const float* __restrict__ x_data, const float* __restrict__ x_time,
               const float* __restrict__ Wu1, const float* __restrict__ bu1,
               const float* __restrict__ Wu2, const float* __restrict__ bu2,
               const float* __restrict__ Wr1, const float* __restrict__ br1,
               const float* __restrict__ Wr2, const float* __restrict__ br2,
               const float* __restrict__ Wn1, const float* __restrict__ bn1,
               const float* __restrict__ Wn2, const float* __restrict__ bn2,
               const float* __restrict__ Wo1, const float* __restrict__ bo1,
               const float* __restrict__ Wo2, const float* __restrict__ bo2,
               const float* __restrict__ Wt1, const float* __restrict__ bt1,
               const float* __restrict__ Wt2, const float* __restrict__ bt2,
               const float* __restrict__ Wt3, const float* __restrict__ bt3,
               float* __restrict__ out) {
    __shared__ SMem sm;
    const int t = threadIdx.x;
    const int row0 = blockIdx.x * RPB;

    // init state
    for (int i = t; i < RPB * Hd; i += NTHR) {
        (&sm.h[0][0])[i] = 0.f;
        (&sm.hs[0][0])[i] = 0.f;
    }
    __syncthreads();

    for (int step = 0; step < Tt; step++) {
        // load x rows for this step + dt
        {
            int r = t / Xd, i = t % Xd;  // NTHR == RPB*Xd == 256
            sm.xv[r][i] = x_data[(long)(row0 + r) * Tt * Xd + (long)step * Xd + i];
        }
        if (t == 0) {
            float dtv;
            if (step == 0)      dtv = -0.01f;
            else if (step == 1) dtv = x_time[Tt - 1] - x_time[0];
            else                dtv = x_time[step - 2] - x_time[step - 1];
            sm.dt = dtv;
        }
        __syncthreads();

        // Phase 1: t1 = tanh(h @ Wo1 + bo1)   (K=512, N=100)
        if (t < RPB * NU) {
            int r = t / NU, j = t % NU;
            sm.t1[r][j] = tanhf(dotN<Hd>(sm.h[r], Wo1, NU, j) + __ldg(&bo1[j]));
        }
        __syncthreads();

        // Phase 2: h_ode = h + dt*(t1 @ Wo2 + bo2)   (K=100, N=512)
        {
            float a00, a01, a10, a11;
            mm100_512(sm.t1[0], sm.t1[1], Wo2, t, a00, a01, a10, a11);
            const float dtv = sm.dt;
            const int j0 = t, j1 = t + 256;
            float b0 = __ldg(&bo2[j0]), b1 = __ldg(&bo2[j1]);
            sm.hode[0][j0] = sm.h[0][j0] + dtv * (a00 + b0);
            sm.hode[0][j1] = sm.h[0][j1] + dtv * (a01 + b1);
            sm.hode[1][j0] = sm.h[1][j0] + dtv * (a10 + b0);
            sm.hode[1][j1] = sm.h[1][j1] + dtv * (a11 + b1);
        }
        __syncthreads();

        // Phase 3 prep: cc = [h_ode, hs, x]
        for (int i = t; i < RPB * CIN; i += NTHR) {
            int r = i / CIN, k = i % CIN;
            float v = (k < Hd) ? sm.hode[r][k]
                               : (k < 2 * Hd ? sm.hs[r][k - Hd] : sm.xv[r][k - 2 * Hd]);
            sm.cc[r][k] = v;
        }
        __syncthreads();

        // Phase 3: u_pre, r_pre = tanh(cc @ W?1 + b?1)   (K=1152, N=100)
        if (t < RPB * NU) {
            int r = t / NU, j = t % NU;
            sm.p1[r][j] = tanhf(dotN<CIN>(sm.cc[r], Wu1, NU, j) + __ldg(&bu1[j]));
            sm.p2[r][j] = tanhf(dotN<CIN>(sm.cc[r], Wr1, NU, j) + __ldg(&br1[j]));
        }
        __syncthreads();

        // Phase 4: u = sigmoid(u_pre @ Wu2 + bu2), r = sigmoid(r_pre @ Wr2 + br2)
        {
            const int j0 = t, j1 = t + 256;
            float a00, a01, a10, a11;
            mm100_512(sm.p1[0], sm.p1[1], Wu2, t, a00, a01, a10, a11);
            float b0 = __ldg(&bu2[j0]), b1 = __ldg(&bu2[j1]);
            sm.ug[0][j0] = sigmoidf_(a00 + b0);
            sm.ug[0][j1] = sigmoidf_(a01 + b1);
            sm.ug[1][j0] = sigmoidf_(a10 + b0);
            sm.ug[1][j1] = sigmoidf_(a11 + b1);

            mm100_512(sm.p2[0], sm.p2[1], Wr2, t, a00, a01, a10, a11);
            b0 = __ldg(&br2[j0]); b1 = __ldg(&br2[j1]);
            sm.rg[0][j0] = sigmoidf_(a00 + b0);
            sm.rg[0][j1] = sigmoidf_(a01 + b1);
            sm.rg[1][j0] = sigmoidf_(a10 + b0);
            sm.rg[1][j1] = sigmoidf_(a11 + b1);
        }
        __syncthreads();

        // Phase 5 prep: cc = [h_ode*r, hs*r, x]
        for (int i = t; i < RPB * CIN; i += NTHR) {
            int r = i / CIN, k = i % CIN;
            float v;
            if (k < Hd)           v = sm.hode[r][k] * sm.rg[r][k];
            else if (k < 2 * Hd)  v = sm.hs[r][k - Hd] * sm.rg[r][k - Hd];
            else                  v = sm.xv[r][k - 2 * Hd];
            sm.cc[r][k] = v;
        }
        __syncthreads();

        // Phase 5: n_pre = tanh(cc @ Wn1 + bn1)   (K=1152, N=100)
        if (t < RPB * NU) {
            int r = t / NU, j = t % NU;
            sm.p1[r][j] = tanhf(dotN<CIN>(sm.cc[r], Wn1, NU, j) + __ldg(&bn1[j]));
        }
        __syncthreads();

        // Phase 6: ns = n_pre @ Wn2 + bn2  (N=1024); state update
        {
            float a[8];
            mm100_1024(sm.p1[0], sm.p1[1], Wn2, t, a);
#pragma unroll
            for (int p = 0; p < 2; p++) {
                const int jm = t + 256 * p;
                const float bm = __ldg(&bn2[jm]);
                const float bs = __ldg(&bn2[jm + Hd]);
#pragma unroll
                for (int r = 0; r < RPB; r++) {
                    float m = a[4 * r + p] + bm;
                    float s = fabsf(a[4 * r + p + 2] + bs);
                    float uu = sm.ug[r][jm];
                    sm.h[r][jm]  = (1.f - uu) * m + uu * sm.hode[r][jm];
                    sm.hs[r][jm] = (1.f - uu) * s + uu * sm.hs[r][jm];
                }
            }
        }
        __syncthreads();
    }

    // ---- Output head ----
    // cc = [hT, hsT]  (K = 1024)
    for (int i = t; i < RPB * 2 * Hd; i += NTHR) {
        int r = i / (2 * Hd), k = i % (2 * Hd);
        sm.cc[r][k] = (k < Hd) ? sm.h[r][k] : sm.hs[r][k - Hd];
    }
    __syncthreads();

    // z1 = tanh(hcat @ Wt1 + bt1)   (K=1024, N=100)
    if (t < RPB * NU) {
        int r = t / NU, j = t % NU;
        sm.t1[r][j] = tanhf(dotN<2 * Hd>(sm.cc[r], Wt1, NU, j) + __ldg(&bt1[j]));
    }
    __syncthreads();

    // z2 = tanh(z1 @ Wt2 + bt2)   (K=100, N=100)
    if (t < RPB * NU) {
        int r = t / NU, j = t % NU;
        sm.p1[r][j] = tanhf(dotN<NU>(sm.t1[r], Wt2, NU, j) + __ldg(&bt2[j]));
    }
    __syncthreads();

    // z3 = z2 @ Wt3 + bt3  (N=1024) -> mu, sigma
    {
        float a[8];
        mm100_1024(sm.p1[0], sm.p1[1], Wt3, t, a);
#pragma unroll
        for (int p = 0; p < 2; p++) {
            const int jm = t + 256 * p;
            const float bm = __ldg(&bt3[jm]);
            const float bs = __ldg(&bt3[jm + Hd]);
#pragma unroll
            for (int r = 0; r < RPB; r++) {
                float mu = a[4 * r + p] + bm;
                float sg = fabsf(a[4 * r + p + 2] + bs);
                out[(long)(row0 + r) * Hd + jm] = mu;
                out[(long)Bsz * Hd + (long)(row0 + r) * Hd + jm] = sg;
            }
        }
    }
}

extern "C" void kernel_launch(void* const* d_in, const int* in_sizes, int n_in,
                              void* d_out, int out_size) {
    const float* x_data = (const float*)d_in[0];
    const float* x_time = (const float*)d_in[1];
    const float* Wu1 = (const float*)d_in[2];
    const float* bu1 = (const float*)d_in[3];
    const float* Wu2 = (const float*)d_in[4];
    const float* bu2 = (const float*)d_in[5];
    const float* Wr1 = (const float*)d_in[6];
    const float* br1 = (const float*)d_in[7];
    const float* Wr2 = (const float*)d_in[8];
    const float* br2 = (const float*)d_in[9];
    const float* Wn1 = (const float*)d_in[10];
    const float* bn1 = (const float*)d_in[11];
    const float* Wn2 = (const float*)d_in[12];
    const float* bn2 = (const float*)d_in[13];
    const float* Wo1 = (const float*)d_in[14];
    const float* bo1 = (const float*)d_in[15];
    const float* Wo2 = (const float*)d_in[16];
    const float* bo2 = (const float*)d_in[17];
    const float* Wt1 = (const float*)d_in[18];
    const float* bt1 = (const float*)d_in[19];
    const float* Wt2 = (const float*)d_in[20];
    const float* bt2 = (const float*)d_in[21];
    const float* Wt3 = (const float*)d_in[22];
    const float* bt3 = (const float*)d_in[23];

    ode_gru_kernel<<<NBLK, NTHR>>>(x_data, x_time,
                                   Wu1, bu1, Wu2, bu2,
                                   Wr1, br1, Wr2, br2,
                                   Wn1, bn1, Wn2, bn2,
                                   Wo1, bo1, Wo2, bo2,
                                   Wt1, bt1, Wt2, bt2, Wt3, bt3,
                                   (float*)d_out);
}

// round 5
// speedup vs baseline: 1.8272x; 1.8272x over previous
#include <cuda_runtime.h>
#include <math.h>

namespace {
constexpr int Bsz = 256;   // batch
constexpr int Tt  = 200;   // time steps
constexpr int Xd  = 128;   // input dim
constexpr int Hd  = 512;   // hidden
constexpr int NU  = 100;   // bottleneck
constexpr int CIN = 2 * Hd + Xd;   // 1152
constexpr int RPB = 2;             // batch rows per CTA
constexpr int NBLK = Bsz / RPB;    // 128 CTAs
constexpr int NTHR = 512;
}

struct SMem {
    float h[RPB][Hd];
    float hs[RPB][Hd];
    float hode[RPB][Hd];
    float ug[RPB][Hd];
    float rg[RPB][Hd];
    float cc[RPB][CIN];
    float xv[RPB][Xd];
    float t1[RPB][NU];
    float p1[RPB][NU];
    float p2[RPB][NU];
    float part[2][RPB][NU];   // K-split partial sums
    float dt;
};

__device__ __forceinline__ float sigmoidf_(float x) {
    return 1.0f / (1.0f + expf(-x));
}

// K must be divisible by 8. dot of smem vector `in` with column j of
// row-major W (K x ldw), 8 independent accumulator chains (MLP>=8).
template <int K>
__device__ __forceinline__ float dot8(const float* __restrict__ in,
                                      const float* __restrict__ W,
                                      int ldw, int j) {
    float a0=0.f,a1=0.f,a2=0.f,a3=0.f,a4=0.f,a5=0.f,a6=0.f,a7=0.f;
    const float* Wp = W + j;
#pragma unroll 2
    for (int k = 0; k < K; k += 8) {
        a0 = fmaf(in[k+0], __ldg(&Wp[(k+0)*ldw]), a0);
        a1 = fmaf(in[k+1], __ldg(&Wp[(k+1)*ldw]), a1);
        a2 = fmaf(in[k+2], __ldg(&Wp[(k+2)*ldw]), a2);
        a3 = fmaf(in[k+3], __ldg(&Wp[(k+3)*ldw]), a3);
        a4 = fmaf(in[k+4], __ldg(&Wp[(k+4)*ldw]), a4);
        a5 = fmaf(in[k+5], __ldg(&Wp[(k+5)*ldw]), a5);
        a6 = fmaf(in[k+6], __ldg(&Wp[(k+6)*ldw]), a6);
        a7 = fmaf(in[k+7], __ldg(&Wp[(k+7)*ldw]), a7);
    }
    return ((a0+a1)+(a2+a3)) + ((a4+a5)+(a6+a7));
}

// K divisible by 4 (used for K=100)
template <int K>
__device__ __forceinline__ float dot4(const float* __restrict__ in,
                                      const float* __restrict__ W,
                                      int ldw, int j) {
    float a0=0.f,a1=0.f,a2=0.f,a3=0.f;
    const float* Wp = W + j;
#pragma unroll 4
    for (int k = 0; k < K; k += 4) {
        a0 = fmaf(in[k+0], __ldg(&Wp[(k+0)*ldw]), a0);
        a1 = fmaf(in[k+1], __ldg(&Wp[(k+1)*ldw]), a1);
        a2 = fmaf(in[k+2], __ldg(&Wp[(k+2)*ldw]), a2);
        a3 = fmaf(in[k+3], __ldg(&Wp[(k+3)*ldw]), a3);
    }
    return (a0+a1)+(a2+a3);
}

// 2 rows (len 100) x W(100 x ldw), thread owns adjacent cols (j, j+1) via
// float2 loads. Produces acc[row][0..1].
__device__ __forceinline__ void mv100_f2(const float* __restrict__ i0v,
                                         const float* __restrict__ i1v,
                                         const float* __restrict__ W,
                                         int ldw, int j,
                                         float2& r0, float2& r1) {
    float2 a0 = make_float2(0.f, 0.f), b0 = a0;
    float2 a1 = a0, b1 = a0;
    const float* Wp = W + j;
#pragma unroll 4
    for (int k = 0; k < NU; k += 2) {
        float2 w0 = __ldg((const float2*)&Wp[(k+0)*ldw]);
        float2 w1 = __ldg((const float2*)&Wp[(k+1)*ldw]);
        float x00 = i0v[k], x01 = i0v[k+1];
        float x10 = i1v[k], x11 = i1v[k+1];
        a0.x = fmaf(x00, w0.x, a0.x); a0.y = fmaf(x00, w0.y, a0.y);
        b0.x = fmaf(x01, w1.x, b0.x); b0.y = fmaf(x01, w1.y, b0.y);
        a1.x = fmaf(x10, w0.x, a1.x); a1.y = fmaf(x10, w0.y, a1.y);
        b1.x = fmaf(x11, w1.x, b1.x); b1.y = fmaf(x11, w1.y, b1.y);
    }
    r0 = make_float2(a0.x + b0.x, a0.y + b0.y);
    r1 = make_float2(a1.x + b1.x, a1.y + b1.y);
}

__global__ void __launch_bounds__(NTHR, 1)
ode_gru_kernel(const float* __restrict__ x_data, const float* __restrict__ x_time,
               const float* __restrict__ Wu1, const float* __restrict__ bu1,
               const float* __restrict__ Wu2, const float* __restrict__ bu2,
               const float* __restrict__ Wr1, const float* __restrict__ br1,
               const float* __restrict__ Wr2, const float* __restrict__ br2,
               const float* __restrict__ Wn1, const float* __restrict__ bn1,
               const float* __restrict__ Wn2, const float* __restrict__ bn2,
               const float* __restrict__ Wo1, const float* __restrict__ bo1,
               const float* __restrict__ Wo2, const float* __restrict__ bo2,
               const float* __restrict__ Wt1, const float* __restrict__ bt1,
               const float* __restrict__ Wt2, const float* __restrict__ bt2,
               const float* __restrict__ Wt3, const float* __restrict__ bt3,
               float* __restrict__ out) {
    __shared__ SMem sm;
    const int t = threadIdx.x;
    const int row0 = blockIdx.x * RPB;

    for (int i = t; i < RPB * Hd; i += NTHR) {
        (&sm.h[0][0])[i] = 0.f;
        (&sm.hs[0][0])[i] = 0.f;
    }
    __syncthreads();

    for (int step = 0; step < Tt; step++) {
        // load x rows + dt
        if (t < RPB * Xd) {
            int r = t / Xd, i = t % Xd;
            sm.xv[r][i] = x_data[(long)(row0 + r) * Tt * Xd + (long)step * Xd + i];
        }
        if (t == 0) {
            float dtv;
            if (step == 0)      dtv = -0.01f;
            else if (step == 1) dtv = x_time[Tt - 1] - x_time[0];
            else                dtv = x_time[step - 2] - x_time[step - 1];
            sm.dt = dtv;
        }
        __syncthreads();

        // Phase 1: t1 = tanh(h @ Wo1 + bo1)  (K=512 split 2x256, N=100)
        if (t < 2 * RPB * NU) {                 // 400 threads
            int split = t / (RPB * NU);
            int rem = t % (RPB * NU);
            int r = rem / NU, j = rem % NU;
            sm.part[split][r][j] =
                dot8<Hd / 2>(sm.h[r] + split * (Hd / 2), Wo1 + split * (Hd / 2) * NU, NU, j);
        }
        __syncthreads();
        if (t < RPB * NU) {
            int r = t / NU, j = t % NU;
            sm.t1[r][j] = tanhf(sm.part[0][r][j] + sm.part[1][r][j] + __ldg(&bo1[j]));
        }
        __syncthreads();

        // Phase 2: h_ode = h + dt*(t1 @ Wo2 + bo2)  (K=100, N=512), float2 cols
        if (t < Hd / 2) {                        // 256 threads
            int j = 2 * t;
            float2 r0, r1;
            mv100_f2(sm.t1[0], sm.t1[1], Wo2, Hd, j, r0, r1);
            const float dtv = sm.dt;
            float2 bb = __ldg((const float2*)&bo2[j]);
            sm.hode[0][j]     = sm.h[0][j]     + dtv * (r0.x + bb.x);
            sm.hode[0][j + 1] = sm.h[0][j + 1] + dtv * (r0.y + bb.y);
            sm.hode[1][j]     = sm.h[1][j]     + dtv * (r1.x + bb.x);
            sm.hode[1][j + 1] = sm.h[1][j + 1] + dtv * (r1.y + bb.y);
        }
        __syncthreads();

        // Phase 3 prep: cc = [h_ode, hs, x]
        for (int i = t; i < RPB * CIN; i += NTHR) {
            int r = i / CIN, k = i % CIN;
            float v = (k < Hd) ? sm.hode[r][k]
                               : (k < 2 * Hd ? sm.hs[r][k - Hd] : sm.xv[r][k - 2 * Hd]);
            sm.cc[r][k] = v;
        }
        __syncthreads();

        // Phase 3: u_pre/r_pre in PARALLEL threads  (K=1152, N=100 x 2 gates)
        if (t < 2 * RPB * NU) {                  // 400 threads
            int gate = t / (RPB * NU);
            int rem = t % (RPB * NU);
            int r = rem / NU, j = rem % NU;
            const float* W = gate ? Wr1 : Wu1;
            const float* bb = gate ? br1 : bu1;
            float v = tanhf(dot8<CIN>(sm.cc[r], W, NU, j) + __ldg(&bb[j]));
            if (gate) sm.p2[r][j] = v; else sm.p1[r][j] = v;
        }
        __syncthreads();

        // Phase 4: u = sig(p1@Wu2+bu2), r = sig(p2@Wr2+br2) in parallel, float2
        {
            int gate = t / (Hd / 2);             // 0: u, 1: r
            int j = 2 * (t % (Hd / 2));
            const float* W2 = gate ? Wr2 : Wu2;
            const float* b2 = gate ? br2 : bu2;
            const float* i0 = gate ? sm.p2[0] : sm.p1[0];
            const float* i1 = gate ? sm.p2[1] : sm.p1[1];
            float2 r0, r1;
            mv100_f2(i0, i1, W2, Hd, j, r0, r1);
            float2 bb = __ldg((const float2*)&b2[j]);
            float (*dst)[Hd] = gate ? sm.rg : sm.ug;
            dst[0][j]     = sigmoidf_(r0.x + bb.x);
            dst[0][j + 1] = sigmoidf_(r0.y + bb.y);
            dst[1][j]     = sigmoidf_(r1.x + bb.x);
            dst[1][j + 1] = sigmoidf_(r1.y + bb.y);
        }
        __syncthreads();

        // Phase 5 prep: cc = [h_ode*r, hs*r, x]
        for (int i = t; i < RPB * CIN; i += NTHR) {
            int r = i / CIN, k = i % CIN;
            float v;
            if (k < Hd)           v = sm.hode[r][k] * sm.rg[r][k];
            else if (k < 2 * Hd)  v = sm.hs[r][k - Hd] * sm.rg[r][k - Hd];
            else                  v = sm.xv[r][k - 2 * Hd];
            sm.cc[r][k] = v;
        }
        __syncthreads();

        // Phase 5: n_pre = tanh(cc @ Wn1 + bn1)  (K=1152 split 2x576, N=100)
        if (t < 2 * RPB * NU) {                  // 400 threads
            int split = t / (RPB * NU);
            int rem = t % (RPB * NU);
            int r = rem / NU, j = rem % NU;
            sm.part[split][r][j] =
                dot8<CIN / 2>(sm.cc[r] + split * (CIN / 2), Wn1 + split * (CIN / 2) * NU, NU, j);
        }
        __syncthreads();
        if (t < RPB * NU) {
            int r = t / NU, j = t % NU;
            sm.p1[r][j] = tanhf(sm.part[0][r][j] + sm.part[1][r][j] + __ldg(&bn1[j]));
        }
        __syncthreads();

        // Phase 6: ns = p1 @ Wn2 + bn2 (N=1024, float2 cols) + state update
        {
            int c = 2 * t;                       // cols c, c+1 of 1024
            float2 r0, r1;
            mv100_f2(sm.p1[0], sm.p1[1], Wn2, 2 * Hd, c, r0, r1);
            float2 bb = __ldg((const float2*)&bn2[c]);
            if (c < Hd) {                        // mean half -> update h
                int j = c;
                float u00 = sm.ug[0][j], u01 = sm.ug[0][j + 1];
                float u10 = sm.ug[1][j], u11 = sm.ug[1][j + 1];
                sm.h[0][j]     = (1.f - u00) * (r0.x + bb.x) + u00 * sm.hode[0][j];
                sm.h[0][j + 1] = (1.f - u01) * (r0.y + bb.y) + u01 * sm.hode[0][j + 1];
                sm.h[1][j]     = (1.f - u10) * (r1.x + bb.x) + u10 * sm.hode[1][j];
                sm.h[1][j + 1] = (1.f - u11) * (r1.y + bb.y) + u11 * sm.hode[1][j + 1];
            } else {                             // std half -> update hs
                int j = c - Hd;
                float u00 = sm.ug[0][j], u01 = sm.ug[0][j + 1];
                float u10 = sm.ug[1][j], u11 = sm.ug[1][j + 1];
                sm.hs[0][j]     = (1.f - u00) * fabsf(r0.x + bb.x) + u00 * sm.hs[0][j];
                sm.hs[0][j + 1] = (1.f - u01) * fabsf(r0.y + bb.y) + u01 * sm.hs[0][j + 1];
                sm.hs[1][j]     = (1.f - u10) * fabsf(r1.x + bb.x) + u10 * sm.hs[1][j];
                sm.hs[1][j + 1] = (1.f - u11) * fabsf(r1.y + bb.y) + u11 * sm.hs[1][j + 1];
            }
        }
        __syncthreads();
    }

    // ---- Output head ----
    // cc = [hT, hsT]  (K = 1024)
    for (int i = t; i < RPB * 2 * Hd; i += NTHR) {
        int r = i / (2 * Hd), k = i % (2 * Hd);
        sm.cc[r][k] = (k < Hd) ? sm.h[r][k] : sm.hs[r][k - Hd];
    }
    __syncthreads();

    // z1 = tanh(hcat @ Wt1 + bt1)  (K=1024 split 2x512, N=100)
    if (t < 2 * RPB * NU) {
        int split = t / (RPB * NU);
        int rem = t % (RPB * NU);
        int r = rem / NU, j = rem % NU;
        sm.part[split][r][j] =
            dot8<Hd>(sm.cc[r] + split * Hd, Wt1 + split * Hd * NU, NU, j);
    }
    __syncthreads();
    if (t < RPB * NU) {
        int r = t / NU, j = t % NU;
        sm.t1[r][j] = tanhf(sm.part[0][r][j] + sm.part[1][r][j] + __ldg(&bt1[j]));
    }
    __syncthreads();

    // z2 = tanh(z1 @ Wt2 + bt2)  (K=100, N=100)
    if (t < RPB * NU) {
        int r = t / NU, j = t % NU;
        sm.p1[r][j] = tanhf(dot4<NU>(sm.t1[r], Wt2, NU, j) + __ldg(&bt2[j]));
    }
    __syncthreads();

    // z3 = z2 @ Wt3 + bt3  (N=1024, float2) -> mu, sigma
    {
        int c = 2 * t;
        float2 r0, r1;
        mv100_f2(sm.p1[0], sm.p1[1], Wt3, 2 * Hd, c, r0, r1);
        float2 bb = __ldg((const float2*)&bt3[c]);
        if (c < Hd) {
            int j = c;
            out[(long)(row0 + 0) * Hd + j]     = r0.x + bb.x;
            out[(long)(row0 + 0) * Hd + j + 1] = r0.y + bb.y;
            out[(long)(row0 + 1) * Hd + j]     = r1.x + bb.x;
            out[(long)(row0 + 1) * Hd + j + 1] = r1.y + bb.y;
        } else {
            int j = c - Hd;
            long base = (long)Bsz * Hd;
            out[base + (long)(row0 + 0) * Hd + j]     = fabsf(r0.x + bb.x);
            out[base + (long)(row0 + 0) * Hd + j + 1] = fabsf(r0.y + bb.y);
            out[base + (long)(row0 + 1) * Hd + j]     = fabsf(r1.x + bb.x);
            out[base + (long)(row0 + 1) * Hd + j + 1] = fabsf(r1.y + bb.y);
        }
    }
}

extern "C" void kernel_launch(void* const* d_in, const int* in_sizes, int n_in,
                              void* d_out, int out_size) {
    const float* x_data = (const float*)d_in[0];
    const float* x_time = (const float*)d_in[1];
    const float* Wu1 = (const float*)d_in[2];
    const float* bu1 = (const float*)d_in[3];
    const float* Wu2 = (const float*)d_in[4];
    const float* bu2 = (const float*)d_in[5];
    const float* Wr1 = (const float*)d_in[6];
    const float* br1 = (const float*)d_in[7];
    const float* Wr2 = (const float*)d_in[8];
    const float* br2 = (const float*)d_in[9];
    const float* Wn1 = (const float*)d_in[10];
    const float* bn1 = (const float*)d_in[11];
    const float* Wn2 = (const float*)d_in[12];
    const float* bn2 = (const float*)d_in[13];
    const float* Wo1 = (const float*)d_in[14];
    const float* bo1 = (const float*)d_in[15];
    const float* Wo2 = (const float*)d_in[16];
    const float* bo2 = (const float*)d_in[17];
    const float* Wt1 = (const float*)d_in[18];
    const float* bt1 = (const float*)d_in[19];
    const float* Wt2 = (const float*)d_in[20];
    const float* bt2 = (const float*)d_in[21];
    const float* Wt3 = (const float*)d_in[22];
    const float* bt3 = (const float*)d_in[23];

    ode_gru_kernel<<<NBLK, NTHR>>>(x_data, x_time,
                                   Wu1, bu1, Wu2, bu2,
                                   Wr1, br1, Wr2, br2,
                                   Wn1, bn1, Wn2, bn2,
                                   Wo1, bo1, Wo2, bo2,
                                   Wt1, bt1, Wt2, bt2, Wt3, bt3,
                                   (float*)d_out);
}

// round 8
// speedup vs baseline: 1.9799x; 1.0836x over previous
#include <cuda_runtime.h>
#include <math.h>

namespace {
constexpr int Bsz = 256;   // batch
constexpr int Tt  = 200;   // time steps
constexpr int Xd  = 128;   // input dim
constexpr int Hd  = 512;   // hidden
constexpr int NU  = 100;   // bottleneck
constexpr int CIN = 2 * Hd + Xd;   // 1152
constexpr int RPB = 2;             // batch rows per CTA
constexpr int NBLK = Bsz / RPB;    // 128 CTAs
constexpr int NTHR = 1024;
}

struct SMem {
    float h[RPB][Hd];
    float hs[RPB][Hd];
    float hode[RPB][Hd];
    float ug[RPB][Hd];
    float rg[RPB][Hd];
    float cc[RPB][CIN];
    float xv[RPB][Xd];
    float t1[RPB][NU];
    float p1[RPB][NU];
    float p2[RPB][NU];
    float part[4][RPB][NU];   // K-split / gate-split partial sums
    float dt;
};

__device__ __forceinline__ float sigmoidf_(float x) {
    return 1.0f / (1.0f + expf(-x));
}

// K divisible by 8. dot of smem vector `in` with column j of row-major W
// (K x ldw), 8 independent accumulator chains.
template <int K>
__device__ __forceinline__ float dot8(const float* __restrict__ in,
                                      const float* __restrict__ W,
                                      int ldw, int j) {
    float a0=0.f,a1=0.f,a2=0.f,a3=0.f,a4=0.f,a5=0.f,a6=0.f,a7=0.f;
    const float* Wp = W + j;
#pragma unroll 2
    for (int k = 0; k < K; k += 8) {
        a0 = fmaf(in[k+0], __ldg(&Wp[(k+0)*ldw]), a0);
        a1 = fmaf(in[k+1], __ldg(&Wp[(k+1)*ldw]), a1);
        a2 = fmaf(in[k+2], __ldg(&Wp[(k+2)*ldw]), a2);
        a3 = fmaf(in[k+3], __ldg(&Wp[(k+3)*ldw]), a3);
        a4 = fmaf(in[k+4], __ldg(&Wp[(k+4)*ldw]), a4);
        a5 = fmaf(in[k+5], __ldg(&Wp[(k+5)*ldw]), a5);
        a6 = fmaf(in[k+6], __ldg(&Wp[(k+6)*ldw]), a6);
        a7 = fmaf(in[k+7], __ldg(&Wp[(k+7)*ldw]), a7);
    }
    return ((a0+a1)+(a2+a3)) + ((a4+a5)+(a6+a7));
}

// K divisible by 4 (used for K=100)
template <int K>
__device__ __forceinline__ float dot4(const float* __restrict__ in,
                                      const float* __restrict__ W,
                                      int ldw, int j) {
    float a0=0.f,a1=0.f,a2=0.f,a3=0.f;
    const float* Wp = W + j;
#pragma unroll 4
    for (int k = 0; k < K; k += 4) {
        a0 = fmaf(in[k+0], __ldg(&Wp[(k+0)*ldw]), a0);
        a1 = fmaf(in[k+1], __ldg(&Wp[(k+1)*ldw]), a1);
        a2 = fmaf(in[k+2], __ldg(&Wp[(k+2)*ldw]), a2);
        a3 = fmaf(in[k+3], __ldg(&Wp[(k+3)*ldw]), a3);
    }
    return (a0+a1)+(a2+a3);
}

// 2 rows (len 100) x col j of W(100 x ldw). 4 accumulator chains.
__device__ __forceinline__ void mv100_col(const float* __restrict__ i0v,
                                          const float* __restrict__ i1v,
                                          const float* __restrict__ W,
                                          int ldw, int j,
                                          float& r0, float& r1) {
    float a00=0.f,a01=0.f,a10=0.f,a11=0.f;
    const float* Wp = W + j;
#pragma unroll 5
    for (int k = 0; k < NU; k += 2) {
        float w0 = __ldg(&Wp[(k+0)*ldw]);
        float w1 = __ldg(&Wp[(k+1)*ldw]);
        a00 = fmaf(i0v[k],   w0, a00);
        a01 = fmaf(i0v[k+1], w1, a01);
        a10 = fmaf(i1v[k],   w0, a10);
        a11 = fmaf(i1v[k+1], w1, a11);
    }
    r0 = a00 + a01;
    r1 = a10 + a11;
}

__global__ void __launch_bounds__(NTHR, 1)
ode_gru_kernel(const float* __restrict__ x_data, const float* __restrict__ x_time,
               const float* __restrict__ Wu1, const float* __restrict__ bu1,
               const float* __restrict__ Wu2, const float* __restrict__ bu2,
               const float* __restrict__ Wr1, const float* __restrict__ br1,
               const float* __restrict__ Wr2, const float* __restrict__ br2,
               const float* __restrict__ Wn1, const float* __restrict__ bn1,
               const float* __restrict__ Wn2, const float* __restrict__ bn2,
               const float* __restrict__ Wo1, const float* __restrict__ bo1,
               const float* __restrict__ Wo2, const float* __restrict__ bo2,
               const float* __restrict__ Wt1, const float* __restrict__ bt1,
               const float* __restrict__ Wt2, const float* __restrict__ bt2,
               const float* __restrict__ Wt3, const float* __restrict__ bt3,
               float* __restrict__ out) {
    __shared__ SMem sm;
    const int t = threadIdx.x;
    const int row0 = blockIdx.x * RPB;

    for (int i = t; i < RPB * Hd; i += NTHR) {
        (&sm.h[0][0])[i] = 0.f;
        (&sm.hs[0][0])[i] = 0.f;
    }
    __syncthreads();

    for (int step = 0; step < Tt; step++) {
        // load x rows + dt
        if (t < RPB * Xd) {
            int r = t / Xd, i = t % Xd;
            sm.xv[r][i] = x_data[(long)(row0 + r) * Tt * Xd + (long)step * Xd + i];
        }
        if (t == 0) {
            float dtv;
            if (step == 0)      dtv = -0.01f;
            else if (step == 1) dtv = x_time[Tt - 1] - x_time[0];
            else                dtv = x_time[step - 2] - x_time[step - 1];
            sm.dt = dtv;
        }
        __syncthreads();

        // Phase 1: t1 = tanh(h @ Wo1 + bo1)  (K=512 split 4x128, N=100)
        if (t < 4 * RPB * NU) {                  // 800 threads
            int split = t / (RPB * NU);
            int rem = t % (RPB * NU);
            int r = rem / NU, j = rem % NU;
            sm.part[split][r][j] =
                dot8<Hd / 4>(sm.h[r] + split * (Hd / 4), Wo1 + split * (Hd / 4) * NU, NU, j);
        }
        __syncthreads();
        if (t < RPB * NU) {
            int r = t / NU, j = t % NU;
            sm.t1[r][j] = tanhf(sm.part[0][r][j] + sm.part[1][r][j] +
                                sm.part[2][r][j] + sm.part[3][r][j] + __ldg(&bo1[j]));
        }
        __syncthreads();

        // Phase 2: h_ode = h + dt*(t1 @ Wo2 + bo2)  (K=100, N=512)
        if (t < Hd) {                            // 512 threads, 1 col each
            int j = t;
            float r0, r1;
            mv100_col(sm.t1[0], sm.t1[1], Wo2, Hd, j, r0, r1);
            const float dtv = sm.dt;
            float bb = __ldg(&bo2[j]);
            sm.hode[0][j] = sm.h[0][j] + dtv * (r0 + bb);
            sm.hode[1][j] = sm.h[1][j] + dtv * (r1 + bb);
        }
        __syncthreads();

        // Phase 3 prep: cc = [h_ode, hs, x]
        for (int i = t; i < RPB * CIN; i += NTHR) {
            int r = i / CIN, k = i % CIN;
            float v = (k < Hd) ? sm.hode[r][k]
                               : (k < 2 * Hd ? sm.hs[r][k - Hd] : sm.xv[r][k - 2 * Hd]);
            sm.cc[r][k] = v;
        }
        __syncthreads();

        // Phase 3: u_pre/r_pre, gates parallel + K-split 2 (K=1152 -> 576)
        if (t < 4 * RPB * NU) {                  // 800 threads
            int tsel = t / (RPB * NU);           // 0..3
            int gate = tsel >> 1;                // 0: u, 1: r
            int split = tsel & 1;
            int rem = t % (RPB * NU);
            int r = rem / NU, j = rem % NU;
            const float* W = gate ? Wr1 : Wu1;
            sm.part[tsel][r][j] =
                dot8<CIN / 2>(sm.cc[r] + split * (CIN / 2), W + split * (CIN / 2) * NU, NU, j);
        }
        __syncthreads();
        if (t < 2 * RPB * NU) {                  // 400 threads
            int gate = t / (RPB * NU);
            int rem = t % (RPB * NU);
            int r = rem / NU, j = rem % NU;
            const float* bb = gate ? br1 : bu1;
            float v = tanhf(sm.part[2 * gate][r][j] + sm.part[2 * gate + 1][r][j] +
                            __ldg(&bb[j]));
            if (gate) sm.p2[r][j] = v; else sm.p1[r][j] = v;
        }
        __syncthreads();

        // Phase 4: u = sig(p1@Wu2+bu2), r = sig(p2@Wr2+br2), 1024 thr 1 col
        {
            int gate = t >> 9;                   // 0: u, 1: r
            int j = t & (Hd - 1);
            const float* W2 = gate ? Wr2 : Wu2;
            const float* b2 = gate ? br2 : bu2;
            const float* i0 = gate ? sm.p2[0] : sm.p1[0];
            const float* i1 = gate ? sm.p2[1] : sm.p1[1];
            float r0, r1;
            mv100_col(i0, i1, W2, Hd, j, r0, r1);
            float bb = __ldg(&b2[j]);
            float (*dst)[Hd] = gate ? sm.rg : sm.ug;
            dst[0][j] = sigmoidf_(r0 + bb);
            dst[1][j] = sigmoidf_(r1 + bb);
        }
        __syncthreads();

        // Phase 5 prep: cc = [h_ode*r, hs*r, x]
        for (int i = t; i < RPB * CIN; i += NTHR) {
            int r = i / CIN, k = i % CIN;
            float v;
            if (k < Hd)           v = sm.hode[r][k] * sm.rg[r][k];
            else if (k < 2 * Hd)  v = sm.hs[r][k - Hd] * sm.rg[r][k - Hd];
            else                  v = sm.xv[r][k - 2 * Hd];
            sm.cc[r][k] = v;
        }
        __syncthreads();

        // Phase 5: n_pre = tanh(cc @ Wn1 + bn1)  (K=1152 split 4x288, N=100)
        if (t < 4 * RPB * NU) {                  // 800 threads
            int split = t / (RPB * NU);
            int rem = t % (RPB * NU);
            int r = rem / NU, j = rem % NU;
            sm.part[split][r][j] =
                dot8<CIN / 4>(sm.cc[r] + split * (CIN / 4), Wn1 + split * (CIN / 4) * NU, NU, j);
        }
        __syncthreads();
        if (t < RPB * NU) {
            int r = t / NU, j = t % NU;
            sm.p1[r][j] = tanhf(sm.part[0][r][j] + sm.part[1][r][j] +
                                sm.part[2][r][j] + sm.part[3][r][j] + __ldg(&bn1[j]));
        }
        __syncthreads();

        // Phase 6: ns = p1 @ Wn2 + bn2 (N=1024, 1024 thr 1 col) + update
        {
            int c = t;                           // col of 1024
            float r0, r1;
            mv100_col(sm.p1[0], sm.p1[1], Wn2, 2 * Hd, c, r0, r1);
            float bb = __ldg(&bn2[c]);
            if (c < Hd) {                        // mean half -> h
                int j = c;
                float u0 = sm.ug[0][j], u1 = sm.ug[1][j];
                sm.h[0][j] = (1.f - u0) * (r0 + bb) + u0 * sm.hode[0][j];
                sm.h[1][j] = (1.f - u1) * (r1 + bb) + u1 * sm.hode[1][j];
            } else {                             // std half -> hs
                int j = c - Hd;
                float u0 = sm.ug[0][j], u1 = sm.ug[1][j];
                sm.hs[0][j] = (1.f - u0) * fabsf(r0 + bb) + u0 * sm.hs[0][j];
                sm.hs[1][j] = (1.f - u1) * fabsf(r1 + bb) + u1 * sm.hs[1][j];
            }
        }
        __syncthreads();
    }

    // ---- Output head (runs once; not perf-critical) ----
    // cc = [hT, hsT]  (K = 1024)
    for (int i = t; i < RPB * 2 * Hd; i += NTHR) {
        int r = i / (2 * Hd), k = i % (2 * Hd);
        sm.cc[r][k] = (k < Hd) ? sm.h[r][k] : sm.hs[r][k - Hd];
    }
    __syncthreads();

    // z1 = tanh(hcat @ Wt1 + bt1)  (K=1024 split 4x256, N=100)
    if (t < 4 * RPB * NU) {
        int split = t / (RPB * NU);
        int rem = t % (RPB * NU);
        int r = rem / NU, j = rem % NU;
        sm.part[split][r][j] =
            dot8<Hd / 2>(sm.cc[r] + split * (Hd / 2), Wt1 + split * (Hd / 2) * NU, NU, j);
    }
    __syncthreads();
    if (t < RPB * NU) {
        int r = t / NU, j = t % NU;
        sm.t1[r][j] = tanhf(sm.part[0][r][j] + sm.part[1][r][j] +
                            sm.part[2][r][j] + sm.part[3][r][j] + __ldg(&bt1[j]));
    }
    __syncthreads();

    // z2 = tanh(z1 @ Wt2 + bt2)  (K=100, N=100)
    if (t < RPB * NU) {
        int r = t / NU, j = t % NU;
        sm.p1[r][j] = tanhf(dot4<NU>(sm.t1[r], Wt2, NU, j) + __ldg(&bt2[j]));
    }
    __syncthreads();

    // z3 = z2 @ Wt3 + bt3  (N=1024, 1024 thr 1 col) -> mu, sigma
    {
        int c = t;
        float r0, r1;
        mv100_col(sm.p1[0], sm.p1[1], Wt3, 2 * Hd, c, r0, r1);
        float bb = __ldg(&bt3[c]);
        if (c < Hd) {
            int j = c;
            out[(long)(row0 + 0) * Hd + j] = r0 + bb;
            out[(long)(row0 + 1) * Hd + j] = r1 + bb;
        } else {
            int j = c - Hd;
            long base = (long)Bsz * Hd;
            out[base + (long)(row0 + 0) * Hd + j] = fabsf(r0 + bb);
            out[base + (long)(row0 + 1) * Hd + j] = fabsf(r1 + bb);
        }
    }
}

extern "C" void kernel_launch(void* const* d_in, const int* in_sizes, int n_in,
                              void* d_out, int out_size) {
    const float* x_data = (const float*)d_in[0];
    const float* x_time = (const float*)d_in[1];
    const float* Wu1 = (const float*)d_in[2];
    const float* bu1 = (const float*)d_in[3];
    const float* Wu2 = (const float*)d_in[4];
    const float* bu2 = (const float*)d_in[5];
    const float* Wr1 = (const float*)d_in[6];
    const float* br1 = (const float*)d_in[7];
    const float* Wr2 = (const float*)d_in[8];
    const float* br2 = (const float*)d_in[9];
    const float* Wn1 = (const float*)d_in[10];
    const float* bn1 = (const float*)d_in[11];
    const float* Wn2 = (const float*)d_in[12];
    const float* bn2 = (const float*)d_in[13];
    const float* Wo1 = (const float*)d_in[14];
    const float* bo1 = (const float*)d_in[15];
    const float* Wo2 = (const float*)d_in[16];
    const float* bo2 = (const float*)d_in[17];
    const float* Wt1 = (const float*)d_in[18];
    const float* bt1 = (const float*)d_in[19];
    const float* Wt2 = (const float*)d_in[20];
    const float* bt2 = (const float*)d_in[21];
    const float* Wt3 = (const float*)d_in[22];
    const float* bt3 = (const float*)d_in[23];

    ode_gru_kernel<<<NBLK, NTHR>>>(x_data, x_time,
                                   Wu1, bu1, Wu2, bu2,
                                   Wr1, br1, Wr2, br2,
                                   Wn1, bn1, Wn2, bn2,
                                   Wo1, bo1, Wo2, bo2,
                                   Wt1, bt1, Wt2, bt2, Wt3, bt3,
                                   (float*)d_out);
}

// round 12
// speedup vs baseline: 3.2037x; 1.6181x over previous
#include <cuda_runtime.h>
#include <math.h>

namespace {
constexpr int Bsz = 256;   // batch
constexpr int Tt  = 200;   // time steps
constexpr int Xd  = 128;   // input dim
constexpr int Hd  = 512;   // hidden
constexpr int NU  = 100;   // bottleneck
constexpr int CIN = 2 * Hd + Xd;   // 1152
constexpr int RPB = 2;             // batch rows per CTA
constexpr int NBLK = Bsz / RPB;    // 128 CTAs
constexpr int NTHR = 1024;
}

struct SMem {
    float h[RPB][Hd];
    float hs[RPB][Hd];
    float hode[RPB][Hd];
    float ug[RPB][Hd];
    float cc[RPB][CIN];
    float t1[RPB][NU];
    float p1[RPB][NU];
    float p2[RPB][NU];
    float spart[4096];   // union: part(s,r,j)=[(s*2+r)*100+j] (16 groups) OR
                         //        part2(s,r,c)=[(s*2+r)*1024+c] (2 splits)
    float dt;
};

__device__ __forceinline__ float sigmoidf_(float x) {
    return 1.0f / (1.0f + expf(-x));
}

// Both batch rows, adjacent col pair. K even. Wp = &W[K0*ldw + j0] (8B aligned).
// in0/in1 = smem vectors offset by K0. Produces o0 (row0: col j0,j0+1), o1 (row1).
template <int K>
__device__ __forceinline__ void dotpair(const float* __restrict__ in0,
                                        const float* __restrict__ in1,
                                        const float* __restrict__ Wp, int ldw,
                                        float2& o0, float2& o1) {
    float a00=0.f,a01=0.f,a10=0.f,a11=0.f;
    float b00=0.f,b01=0.f,b10=0.f,b11=0.f;
#pragma unroll 4
    for (int k = 0; k < K; k += 2) {
        float2 w0 = __ldg((const float2*)(Wp + (k    ) * ldw));
        float2 w1 = __ldg((const float2*)(Wp + (k + 1) * ldw));
        float x00 = in0[k], x01 = in0[k + 1];
        float x10 = in1[k], x11 = in1[k + 1];
        a00 = fmaf(x00, w0.x, a00); a01 = fmaf(x00, w0.y, a01);
        a10 = fmaf(x10, w0.x, a10); a11 = fmaf(x10, w0.y, a11);
        b00 = fmaf(x01, w1.x, b00); b01 = fmaf(x01, w1.y, b01);
        b10 = fmaf(x11, w1.x, b10); b11 = fmaf(x11, w1.y, b11);
    }
    o0 = make_float2(a00 + b00, a01 + b01);
    o1 = make_float2(a10 + b10, a11 + b11);
}

// scalar column dot, 4 chains (head only, K=100)
template <int K>
__device__ __forceinline__ float dot4(const float* __restrict__ in,
                                      const float* __restrict__ W,
                                      int ldw, int j) {
    float a0=0.f,a1=0.f,a2=0.f,a3=0.f;
    const float* Wp = W + j;
#pragma unroll 4
    for (int k = 0; k < K; k += 4) {
        a0 = fmaf(in[k+0], __ldg(&Wp[(k+0)*ldw]), a0);
        a1 = fmaf(in[k+1], __ldg(&Wp[(k+1)*ldw]), a1);
        a2 = fmaf(in[k+2], __ldg(&Wp[(k+2)*ldw]), a2);
        a3 = fmaf(in[k+3], __ldg(&Wp[(k+3)*ldw]), a3);
    }
    return (a0+a1)+(a2+a3);
}

__global__ void __launch_bounds__(NTHR, 1)
ode_gru_kernel(const float* __restrict__ x_data, const float* __restrict__ x_time,
               const float* __restrict__ Wu1, const float* __restrict__ bu1,
               const float* __restrict__ Wu2, const float* __restrict__ bu2,
               const float* __restrict__ Wr1, const float* __restrict__ br1,
               const float* __restrict__ Wr2, const float* __restrict__ br2,
               const float* __restrict__ Wn1, const float* __restrict__ bn1,
               const float* __restrict__ Wn2, const float* __restrict__ bn2,
               const float* __restrict__ Wo1, const float* __restrict__ bo1,
               const float* __restrict__ Wo2, const float* __restrict__ bo2,
               const float* __restrict__ Wt1, const float* __restrict__ bt1,
               const float* __restrict__ Wt2, const float* __restrict__ bt2,
               const float* __restrict__ Wt3, const float* __restrict__ bt3,
               float* __restrict__ out) {
    __shared__ SMem sm;
    const int t = threadIdx.x;
    const int row0 = blockIdx.x * RPB;

    // init state; cc hs-part must be 0 for step 0's P3
    for (int i = t; i < RPB * Hd; i += NTHR) {
        (&sm.h[0][0])[i] = 0.f;
        (&sm.hs[0][0])[i] = 0.f;
        int r = i / Hd, j = i % Hd;
        sm.cc[r][Hd + j] = 0.f;
    }
    __syncthreads();

    for (int step = 0; step < Tt; step++) {
        // x loader -> cc x-part; dt
        if (t < RPB * Xd) {
            int r = t / Xd, i = t % Xd;
            sm.cc[r][2 * Hd + i] =
                x_data[(long)(row0 + r) * Tt * Xd + (long)step * Xd + i];
        }
        if (t == 0) {
            float dtv;
            if (step == 0)      dtv = -0.01f;
            else if (step == 1) dtv = x_time[Tt - 1] - x_time[0];
            else                dtv = x_time[step - 2] - x_time[step - 1];
            sm.dt = dtv;
        }
        __syncthreads();

        // P1: partials of h @ Wo1  (K=512 -> 16 splits of 32; 50 col-pairs)
        if (t < 800) {
            int s = t / 50, jp = t % 50, j0 = 2 * jp;
            int K0 = s * 32;
            float2 o0, o1;
            dotpair<32>(sm.h[0] + K0, sm.h[1] + K0, Wo1 + K0 * NU + j0, NU, o0, o1);
            float* P = sm.spart + (s * 2) * NU + j0;
            P[0] = o0.x; P[1] = o0.y;            // row 0: group s*2
            P[NU] = o1.x; P[NU + 1] = o1.y;      // row 1: group s*2+1
        }
        __syncthreads();
        // P1c: t1 = tanh(sum + bo1)
        if (t < RPB * NU) {
            int r = t / NU, j = t % NU;
            float sum = __ldg(&bo1[j]);
#pragma unroll
            for (int s = 0; s < 16; s++) sum += sm.spart[(s * 2 + r) * NU + j];
            sm.t1[r][j] = tanhf(sum);
        }
        __syncthreads();

        // P2: partials of t1 @ Wo2  (K=100 -> 2 splits of 50; 256 col-pairs)
        if (t < 512) {
            int s = t / 256, jp = t % 256, j0 = 2 * jp;
            int K0 = s * 50;
            float2 o0, o1;
            dotpair<50>(sm.t1[0] + K0, sm.t1[1] + K0, Wo2 + K0 * Hd + j0, Hd, o0, o1);
            float* P = sm.spart + (s * 2) * 1024 + j0;
            P[0] = o0.x; P[1] = o0.y;
            P[1024] = o1.x; P[1024 + 1] = o1.y;
        }
        __syncthreads();
        // P2c: hode = h + dt*(sum + bo2); also cc h-part
        if (t < Hd) {
            int j = t;
            float bb = __ldg(&bo2[j]);
            float dtv = sm.dt;
#pragma unroll
            for (int r = 0; r < RPB; r++) {
                float v = sm.spart[r * 1024 + j] + sm.spart[(2 + r) * 1024 + j] + bb;
                float ho = sm.h[r][j] + dtv * v;
                sm.hode[r][j] = ho;
                sm.cc[r][j] = ho;
            }
        }
        __syncthreads();

        // P3: partials of cc @ {Wu1,Wr1}  (K=1152 -> 8 splits of 144; 2 gates)
        if (t < 800) {
            int g = t / 400, rem = t % 400;
            int s = rem / 50, jp = rem % 50, j0 = 2 * jp;
            int K0 = s * 144;
            const float* W = g ? Wr1 : Wu1;
            float2 o0, o1;
            dotpair<144>(sm.cc[0] + K0, sm.cc[1] + K0, W + K0 * NU + j0, NU, o0, o1);
            float* P = sm.spart + ((g * 8 + s) * 2) * NU + j0;
            P[0] = o0.x; P[1] = o0.y;
            P[NU] = o1.x; P[NU + 1] = o1.y;
        }
        __syncthreads();
        // P3c: p1/p2 = tanh(sum + b)
        if (t < 400) {
            int g = t / 200, rem = t % 200;
            int r = rem / NU, j = rem % NU;
            float sum = __ldg(&(g ? br1 : bu1)[j]);
#pragma unroll
            for (int s = 0; s < 8; s++)
                sum += sm.spart[((g * 8 + s) * 2 + r) * NU + j];
            float v = tanhf(sum);
            if (g) sm.p2[r][j] = v; else sm.p1[r][j] = v;
        }
        __syncthreads();

        // P4: partials of {p1@Wu2, p2@Wr2}  (K=100 -> 2 splits; 2 gates x 256 pairs)
        {
            int g = t / 512, rem = t % 512;
            int s = rem / 256, jp = rem % 256, j0 = 2 * jp;
            int K0 = s * 50;
            const float* W2 = g ? Wr2 : Wu2;
            const float* i0 = g ? sm.p2[0] : sm.p1[0];
            const float* i1 = g ? sm.p2[1] : sm.p1[1];
            float2 o0, o1;
            dotpair<50>(i0 + K0, i1 + K0, W2 + K0 * Hd + j0, Hd, o0, o1);
            float* P = sm.spart + (s * 2) * 1024 + g * Hd + j0;
            P[0] = o0.x; P[1] = o0.y;
            P[1024] = o1.x; P[1024 + 1] = o1.y;
        }
        __syncthreads();
        // P4c: u -> ug; r -> write r-scaled cc directly
        {
            int g = t / 512, j = t % 512;
            float bb = __ldg(&(g ? br2 : bu2)[j]);
            int c = g * Hd + j;
#pragma unroll
            for (int r = 0; r < RPB; r++) {
                float v = sm.spart[r * 1024 + c] + sm.spart[(2 + r) * 1024 + c] + bb;
                float gv = sigmoidf_(v);
                if (g == 0) {
                    sm.ug[r][j] = gv;
                } else {
                    sm.cc[r][j]      = sm.hode[r][j] * gv;
                    sm.cc[r][Hd + j] = sm.hs[r][j] * gv;
                }
            }
        }
        __syncthreads();

        // P5: partials of cc_r @ Wn1  (K=1152 -> 16 splits of 72)
        if (t < 800) {
            int s = t / 50, jp = t % 50, j0 = 2 * jp;
            int K0 = s * 72;
            float2 o0, o1;
            dotpair<72>(sm.cc[0] + K0, sm.cc[1] + K0, Wn1 + K0 * NU + j0, NU, o0, o1);
            float* P = sm.spart + (s * 2) * NU + j0;
            P[0] = o0.x; P[1] = o0.y;
            P[NU] = o1.x; P[NU + 1] = o1.y;
        }
        __syncthreads();
        // P5c
        if (t < RPB * NU) {
            int r = t / NU, j = t % NU;
            float sum = __ldg(&bn1[j]);
#pragma unroll
            for (int s = 0; s < 16; s++) sum += sm.spart[(s * 2 + r) * NU + j];
            sm.p1[r][j] = tanhf(sum);
        }
        __syncthreads();

        // P6: partials of p1 @ Wn2  (N=1024, K=100 -> 2 splits; 512 pairs)
        {
            int s = t / 512, jp = t % 512, j0 = 2 * jp;
            int K0 = s * 50;
            float2 o0, o1;
            dotpair<50>(sm.p1[0] + K0, sm.p1[1] + K0, Wn2 + K0 * 2 * Hd + j0,
                        2 * Hd, o0, o1);
            float* P = sm.spart + (s * 2) * 1024 + j0;
            P[0] = o0.x; P[1] = o0.y;
            P[1024] = o1.x; P[1024 + 1] = o1.y;
        }
        __syncthreads();
        // P6c: state update; also next-step cc hs-part
        {
            int c = t;
            float bb = __ldg(&bn2[c]);
#pragma unroll
            for (int r = 0; r < RPB; r++) {
                float v = sm.spart[r * 1024 + c] + sm.spart[(2 + r) * 1024 + c] + bb;
                if (c < Hd) {
                    int j = c;
                    float u = sm.ug[r][j];
                    sm.h[r][j] = (1.f - u) * v + u * sm.hode[r][j];
                } else {
                    int j = c - Hd;
                    float u = sm.ug[r][j];
                    float ns = (1.f - u) * fabsf(v) + u * sm.hs[r][j];
                    sm.hs[r][j] = ns;
                    sm.cc[r][Hd + j] = ns;   // hs-part of cc for next step
                }
            }
        }
        __syncthreads();
    }

    // ---- Output head (runs once) ----
    // cc = [hT, hsT]
    for (int i = t; i < RPB * 2 * Hd; i += NTHR) {
        int r = i / (2 * Hd), k = i % (2 * Hd);
        sm.cc[r][k] = (k < Hd) ? sm.h[r][k] : sm.hs[r][k - Hd];
    }
    __syncthreads();

    // z1 = tanh(hcat @ Wt1 + bt1)  (K=1024 -> 16 splits of 64)
    if (t < 800) {
        int s = t / 50, jp = t % 50, j0 = 2 * jp;
        int K0 = s * 64;
        float2 o0, o1;
        dotpair<64>(sm.cc[0] + K0, sm.cc[1] + K0, Wt1 + K0 * NU + j0, NU, o0, o1);
        float* P = sm.spart + (s * 2) * NU + j0;
        P[0] = o0.x; P[1] = o0.y;
        P[NU] = o1.x; P[NU + 1] = o1.y;
    }
    __syncthreads();
    if (t < RPB * NU) {
        int r = t / NU, j = t % NU;
        float sum = __ldg(&bt1[j]);
#pragma unroll
        for (int s = 0; s < 16; s++) sum += sm.spart[(s * 2 + r) * NU + j];
        sm.t1[r][j] = tanhf(sum);
    }
    __syncthreads();

    // z2 = tanh(z1 @ Wt2 + bt2)  (K=100, N=100)
    if (t < RPB * NU) {
        int r = t / NU, j = t % NU;
        sm.p1[r][j] = tanhf(dot4<NU>(sm.t1[r], Wt2, NU, j) + __ldg(&bt2[j]));
    }
    __syncthreads();

    // z3 = z2 @ Wt3 + bt3  (N=1024, K=100 -> 2 splits)
    {
        int s = t / 512, jp = t % 512, j0 = 2 * jp;
        int K0 = s * 50;
        float2 o0, o1;
        dotpair<50>(sm.p1[0] + K0, sm.p1[1] + K0, Wt3 + K0 * 2 * Hd + j0,
                    2 * Hd, o0, o1);
        float* P = sm.spart + (s * 2) * 1024 + j0;
        P[0] = o0.x; P[1] = o0.y;
        P[1024] = o1.x; P[1024 + 1] = o1.y;
    }
    __syncthreads();
    {
        int c = t;
        float bb = __ldg(&bt3[c]);
#pragma unroll
        for (int r = 0; r < RPB; r++) {
            float v = sm.spart[r * 1024 + c] + sm.spart[(2 + r) * 1024 + c] + bb;
            if (c < Hd) {
                out[(long)(row0 + r) * Hd + c] = v;
            } else {
                long base = (long)Bsz * Hd;
                out[base + (long)(row0 + r) * Hd + (c - Hd)] = fabsf(v);
            }
        }
    }
}

extern "C" void kernel_launch(void* const* d_in, const int* in_sizes, int n_in,
                              void* d_out, int out_size) {
    const float* x_data = (const float*)d_in[0];
    const float* x_time = (const float*)d_in[1];
    const float* Wu1 = (const float*)d_in[2];
    const float* bu1 = (const float*)d_in[3];
    const float* Wu2 = (const float*)d_in[4];
    const float* bu2 = (const float*)d_in[5];
    const float* Wr1 = (const float*)d_in[6];
    const float* br1 = (const float*)d_in[7];
    const float* Wr2 = (const float*)d_in[8];
    const float* br2 = (const float*)d_in[9];
    const float* Wn1 = (const float*)d_in[10];
    const float* bn1 = (const float*)d_in[11];
    const float* Wn2 = (const float*)d_in[12];
    const float* bn2 = (const float*)d_in[13];
    const float* Wo1 = (const float*)d_in[14];
    const float* bo1 = (const float*)d_in[15];
    const float* Wo2 = (const float*)d_in[16];
    const float* bo2 = (const float*)d_in[17];
    const float* Wt1 = (const float*)d_in[18];
    const float* bt1 = (const float*)d_in[19];
    const float* Wt2 = (const float*)d_in[20];
    const float* bt2 = (const float*)d_in[21];
    const float* Wt3 = (const float*)d_in[22];
    const float* bt3 = (const float*)d_in[23];

    ode_gru_kernel<<<NBLK, NTHR>>>(x_data, x_time,
                                   Wu1, bu1, Wu2, bu2,
                                   Wr1, br1, Wr2, br2,
                                   Wn1, bn1, Wn2, bn2,
                                   Wo1, bo1, Wo2, bo2,
                                   Wt1, bt1, Wt2, bt2, Wt3, bt3,
                                   (float*)d_out);
}